// round 1
// baseline (speedup 1.0000x reference)
#include <cuda_runtime.h>
#include <math.h>

// Problem constants (fixed by the dataset)
#define HH 512
#define WW 512
#define MAXV 2048
#define MAXF 4096
#define VIEW_TAN 0.5773502691896258f   // tan(30 deg)
#define NEARP 0.1f
#define BIGZ 1.0e10f
#define CH 128          // faces per shared-memory chunk
#define NBLK (32*32)    // render grid blocks

// ---------------- device scratch (no allocations allowed) ----------------
__device__ float g_vx[MAXV];
__device__ float g_vy[MAXV];
__device__ float g_vz[MAXV];
// Per-face data, 3 x float4 = 12 floats:
//  FA = {A0, B0, C0, A1}
//  FB = {B1, C1, A2, B2}
//  FC = {C2, Z0*inv, Z1*inv, Z2*inv}
__device__ float4 g_FA[MAXF];
__device__ float4 g_FB[MAXF];
__device__ float4 g_FC[MAXF];
__device__ float4 g_COL[MAXF];
__device__ float  g_partials[NBLK];

// ---------------- kernel 1: camera + vertex transform ----------------
__global__ void k_verts(const float* __restrict__ v,
                        const float* __restrict__ campos,
                        const float* __restrict__ camup,
                        int nV) {
    __shared__ float R[9];
    __shared__ float eye[3];
    if (threadIdx.x == 0) {
        float ex = campos[0], ey = campos[1], ez = campos[2];
        // z_axis = normalize(-eye)
        float nx = -ex, ny = -ey, nz = -ez;
        float nl = sqrtf(nx*nx + ny*ny + nz*nz) + 1e-12f;
        float zx = nx/nl, zy = ny/nl, zz = nz/nl;
        // normalize(up)
        float ux = camup[0], uy = camup[1], uz = camup[2];
        float ul = sqrtf(ux*ux + uy*uy + uz*uz) + 1e-12f;
        ux /= ul; uy /= ul; uz /= ul;
        // x_axis = normalize(cross(u, z))
        float cx = uy*zz - uz*zy;
        float cy = uz*zx - ux*zz;
        float cz = ux*zy - uy*zx;
        float cl = sqrtf(cx*cx + cy*cy + cz*cz) + 1e-12f;
        float xx = cx/cl, xy = cy/cl, xz = cz/cl;
        // y_axis = cross(z, x)
        float yx = zy*xz - zz*xy;
        float yy = zz*xx - zx*xz;
        float yz = zx*xy - zy*xx;
        R[0]=xx; R[1]=xy; R[2]=xz;
        R[3]=yx; R[4]=yy; R[5]=yz;
        R[6]=zx; R[7]=zy; R[8]=zz;
        eye[0]=ex; eye[1]=ey; eye[2]=ez;
    }
    __syncthreads();
    for (int i = threadIdx.x; i < nV; i += blockDim.x) {
        float ax = v[3*i+0] - eye[0];
        float ay = v[3*i+1] - eye[1];
        float az = v[3*i+2] - eye[2];
        float cxx = R[0]*ax + R[1]*ay + R[2]*az;
        float cyy = R[3]*ax + R[4]*ay + R[5]*az;
        float czz = R[6]*ax + R[7]*ay + R[8]*az;
        float d = czz * VIEW_TAN + 1e-12f;
        g_vx[i] = cxx / d;
        g_vy[i] = cyy / d;
        g_vz[i] = czz;
    }
}

// ---------------- kernel 2: per-face setup ----------------
__global__ void k_faces(const int* __restrict__ faces,
                        const float* __restrict__ tex,
                        int nF) {
    int f = blockIdx.x * blockDim.x + threadIdx.x;
    if (f >= nF) return;
    int i0 = faces[3*f+0], i1 = faces[3*f+1], i2 = faces[3*f+2];
    float p0x = g_vx[i0], p0y = g_vy[i0], z0 = g_vz[i0];
    float p1x = g_vx[i1], p1y = g_vy[i1], z1 = g_vz[i1];
    float p2x = g_vx[i2], p2y = g_vy[i2], z2 = g_vz[i2];

    float area = (p1x-p0x)*(p2y-p0y) - (p1y-p0y)*(p2x-p0x);

    float4 FA, FB, FC;
    if (fabsf(area) > 1e-8f) {
        float s   = (area > 0.0f) ? 1.0f : -1.0f;
        float inv = 1.0f / fabsf(area);
        // edge0: e = p2-p1, ref point p1  (w0 = cross2(p2-p1, d-p1))
        float e0x = (p2x-p1x)*s, e0y = (p2y-p1y)*s;
        float A0 = -e0y, B0 = e0x, C0 = e0y*p1x - e0x*p1y;
        // edge1: e = p0-p2, ref point p2
        float e1x = (p0x-p2x)*s, e1y = (p0y-p2y)*s;
        float A1 = -e1y, B1 = e1x, C1 = e1y*p2x - e1x*p2y;
        // edge2: e = p1-p0, ref point p0
        float e2x = (p1x-p0x)*s, e2y = (p1y-p0y)*s;
        float A2 = -e2y, B2 = e2x, C2 = e2y*p0x - e2x*p0y;
        FA = make_float4(A0, B0, C0, A1);
        FB = make_float4(B1, C1, A2, B2);
        FC = make_float4(C2, z0*inv, z1*inv, z2*inv);
    } else {
        // degenerate: force all edge functions negative -> never inside
        FA = make_float4(0.f, 0.f, -1.f, 0.f);
        FB = make_float4(0.f, -1.f, 0.f, 0.f);
        FC = make_float4(-1.f, 0.f, 0.f, 0.f);
    }
    g_FA[f] = FA; g_FB[f] = FB; g_FC[f] = FC;

    // color = mean over 2x2x2 texels (8 samples x 3 channels)
    const float* t = tex + (size_t)f * 24;
    float r = 0.f, g = 0.f, b = 0.f;
    #pragma unroll
    for (int k = 0; k < 8; k++) {
        r += t[3*k+0]; g += t[3*k+1]; b += t[3*k+2];
    }
    g_COL[f] = make_float4(r*0.125f, g*0.125f, b*0.125f, 0.f);
}

// ---------------- kernel 3: rasterize + per-block loss partials ----------------
__global__ __launch_bounds__(256)
void k_render(const float* __restrict__ image_ref, int nF) {
    __shared__ float4 sA[CH];
    __shared__ float4 sB[CH];
    __shared__ float4 sC[CH];

    const int tx = threadIdx.x, ty = threadIdx.y;
    const int x = blockIdx.x * 16 + tx;
    const int y = blockIdx.y * 16 + ty;
    const int tid = ty * 16 + tx;

    const float px = (x + 0.5f) * (2.0f / WW) - 1.0f;
    const float py = 1.0f - (y + 0.5f) * (2.0f / HH);

    float zbest = BIGZ;
    int   best  = -1;

    for (int base = 0; base < nF; base += CH) {
        int cnt = min(CH, nF - base);
        __syncthreads();
        for (int i = tid; i < cnt; i += 256) {
            sA[i] = g_FA[base + i];
            sB[i] = g_FB[base + i];
            sC[i] = g_FC[base + i];
        }
        __syncthreads();

        #pragma unroll 4
        for (int i = 0; i < cnt; i++) {
            float4 fa = sA[i];
            float4 fb = sB[i];
            float4 fc = sC[i];
            float u0 = fmaf(fa.x, px, fmaf(fa.y, py, fa.z));
            float u1 = fmaf(fa.w, px, fmaf(fb.x, py, fb.y));
            float u2 = fmaf(fb.z, px, fmaf(fb.w, py, fc.x));
            float z  = fmaf(u0, fc.y, fmaf(u1, fc.z, u2 * fc.w));
            float m  = fminf(u0, fminf(u1, u2));
            if (m >= 0.0f && z > NEARP && z < zbest) {
                zbest = z;
                best  = base + i;
            }
        }
    }

    float r = 0.f, g = 0.f, b = 0.f;
    if (best >= 0) {
        float4 c = g_COL[best];
        r = c.x; g = c.y; b = c.z;
    }

    // vertical flip: rendered row y compares against image_ref row H-1-y
    const int ry = HH - 1 - y;
    float d0 = r - image_ref[0*HH*WW + ry*WW + x];
    float d1 = g - image_ref[1*HH*WW + ry*WW + x];
    float d2 = b - image_ref[2*HH*WW + ry*WW + x];
    float loss = d0*d0 + d1*d1 + d2*d2;

    __shared__ float red[256];
    red[tid] = loss;
    __syncthreads();
    #pragma unroll
    for (int s = 128; s > 0; s >>= 1) {
        if (tid < s) red[tid] += red[tid + s];
        __syncthreads();
    }
    if (tid == 0) g_partials[blockIdx.y * gridDim.x + blockIdx.x] = red[0];
}

// ---------------- kernel 4: final deterministic reduction ----------------
__global__ void k_reduce(float* __restrict__ out) {
    __shared__ float red[256];
    float s = 0.f;
    for (int i = threadIdx.x; i < NBLK; i += 256) s += g_partials[i];
    red[threadIdx.x] = s;
    __syncthreads();
    #pragma unroll
    for (int st = 128; st > 0; st >>= 1) {
        if (threadIdx.x < st) red[threadIdx.x] += red[threadIdx.x + st];
        __syncthreads();
    }
    if (threadIdx.x == 0) out[0] = red[0];
}

// ---------------- entry point ----------------
extern "C" void kernel_launch(void* const* d_in, const int* in_sizes, int n_in,
                              void* d_out, int out_size) {
    const float* v         = (const float*)d_in[0];   // (1, V, 3)
    const int*   faces     = (const int*)  d_in[1];   // (1, F, 3)
    const float* tex       = (const float*)d_in[2];   // (1, F, 2,2,2,3)
    const float* campos    = (const float*)d_in[3];   // (3,)
    const float* camup     = (const float*)d_in[4];   // (3,)
    const float* image_ref = (const float*)d_in[5];   // (1, 3, H, W)

    int nV = in_sizes[0] / 3;
    int nF = in_sizes[1] / 3;

    k_verts<<<1, 256>>>(v, campos, camup, nV);
    k_faces<<<(nF + 255) / 256, 256>>>(faces, tex, nF);
    k_render<<<dim3(WW/16, HH/16), dim3(16, 16)>>>(image_ref, nF);
    k_reduce<<<1, 256>>>((float*)d_out);
}

// round 2
// speedup vs baseline: 2.4388x; 2.4388x over previous
#include <cuda_runtime.h>
#include <math.h>

// Problem constants (fixed by the dataset)
#define HH 512
#define WW 512
#define MAXV 2048
#define MAXF 4096
#define VIEW_TAN 0.5773502691896258f   // tan(30 deg)
#define NEARP 0.1f
#define BIGZ 1.0e10f
#define CH 256          // faces per culling chunk (= block size)
#define TILE_W 16
#define TILE_H 32       // 2 pixels per thread in y
#define NBX (WW / TILE_W)   // 32
#define NBY (HH / TILE_H)   // 16
#define NBLK (NBX * NBY)    // 512

// ---------------- device scratch (no allocations allowed) ----------------
__device__ float g_vx[MAXV];
__device__ float g_vy[MAXV];
__device__ float g_vz[MAXV];
// Per-face data, 3 x float4 = 12 floats:
//  FA = {A0, B0, C0, A1}
//  FB = {B1, C1, A2, B2}
//  FC = {C2, Z0*inv, Z1*inv, Z2*inv}
__device__ float4 g_FA[MAXF];
__device__ float4 g_FB[MAXF];
__device__ float4 g_FC[MAXF];
__device__ float4 g_BB[MAXF];    // bbox: xmin, ymin, xmax, ymax (NDC)
__device__ float4 g_COL[MAXF];
__device__ float  g_partials[NBLK];

// ---------------- kernel 1: camera + vertex transform ----------------
__global__ void k_verts(const float* __restrict__ v,
                        const float* __restrict__ campos,
                        const float* __restrict__ camup,
                        int nV) {
    __shared__ float R[9];
    __shared__ float eye[3];
    if (threadIdx.x == 0) {
        float ex = campos[0], ey = campos[1], ez = campos[2];
        float nx = -ex, ny = -ey, nz = -ez;
        float nl = sqrtf(nx*nx + ny*ny + nz*nz) + 1e-12f;
        float zx = nx/nl, zy = ny/nl, zz = nz/nl;
        float ux = camup[0], uy = camup[1], uz = camup[2];
        float ul = sqrtf(ux*ux + uy*uy + uz*uz) + 1e-12f;
        ux /= ul; uy /= ul; uz /= ul;
        float cx = uy*zz - uz*zy;
        float cy = uz*zx - ux*zz;
        float cz = ux*zy - uy*zx;
        float cl = sqrtf(cx*cx + cy*cy + cz*cz) + 1e-12f;
        float xx = cx/cl, xy = cy/cl, xz = cz/cl;
        float yx = zy*xz - zz*xy;
        float yy = zz*xx - zx*xz;
        float yz = zx*xy - zy*xx;
        R[0]=xx; R[1]=xy; R[2]=xz;
        R[3]=yx; R[4]=yy; R[5]=yz;
        R[6]=zx; R[7]=zy; R[8]=zz;
        eye[0]=ex; eye[1]=ey; eye[2]=ez;
    }
    __syncthreads();
    for (int i = threadIdx.x; i < nV; i += blockDim.x) {
        float ax = v[3*i+0] - eye[0];
        float ay = v[3*i+1] - eye[1];
        float az = v[3*i+2] - eye[2];
        float cxx = R[0]*ax + R[1]*ay + R[2]*az;
        float cyy = R[3]*ax + R[4]*ay + R[5]*az;
        float czz = R[6]*ax + R[7]*ay + R[8]*az;
        float d = czz * VIEW_TAN + 1e-12f;
        g_vx[i] = cxx / d;
        g_vy[i] = cyy / d;
        g_vz[i] = czz;
    }
}

// ---------------- kernel 2: per-face setup (edges, z coeffs, bbox, color) ----
__global__ void k_faces(const int* __restrict__ faces,
                        const float* __restrict__ tex,
                        int nF) {
    int f = blockIdx.x * blockDim.x + threadIdx.x;
    if (f >= nF) return;
    int i0 = faces[3*f+0], i1 = faces[3*f+1], i2 = faces[3*f+2];
    float p0x = g_vx[i0], p0y = g_vy[i0], z0 = g_vz[i0];
    float p1x = g_vx[i1], p1y = g_vy[i1], z1 = g_vz[i1];
    float p2x = g_vx[i2], p2y = g_vy[i2], z2 = g_vz[i2];

    float area = (p1x-p0x)*(p2y-p0y) - (p1y-p0y)*(p2x-p0x);

    float4 FA, FB, FC, BB;
    if (fabsf(area) > 1e-8f) {
        float s   = (area > 0.0f) ? 1.0f : -1.0f;
        float inv = 1.0f / fabsf(area);
        float e0x = (p2x-p1x)*s, e0y = (p2y-p1y)*s;
        float A0 = -e0y, B0 = e0x, C0 = e0y*p1x - e0x*p1y;
        float e1x = (p0x-p2x)*s, e1y = (p0y-p2y)*s;
        float A1 = -e1y, B1 = e1x, C1 = e1y*p2x - e1x*p2y;
        float e2x = (p1x-p0x)*s, e2y = (p1y-p0y)*s;
        float A2 = -e2y, B2 = e2x, C2 = e2y*p0x - e2x*p0y;
        FA = make_float4(A0, B0, C0, A1);
        FB = make_float4(B1, C1, A2, B2);
        FC = make_float4(C2, z0*inv, z1*inv, z2*inv);
        BB = make_float4(fminf(p0x, fminf(p1x, p2x)),
                         fminf(p0y, fminf(p1y, p2y)),
                         fmaxf(p0x, fmaxf(p1x, p2x)),
                         fmaxf(p0y, fmaxf(p1y, p2y)));
    } else {
        FA = make_float4(0.f, 0.f, -1.f, 0.f);
        FB = make_float4(0.f, -1.f, 0.f, 0.f);
        FC = make_float4(-1.f, 0.f, 0.f, 0.f);
        BB = make_float4(2e9f, 2e9f, -2e9f, -2e9f);   // never overlaps any tile
    }
    g_FA[f] = FA; g_FB[f] = FB; g_FC[f] = FC; g_BB[f] = BB;

    const float* t = tex + (size_t)f * 24;
    float r = 0.f, g = 0.f, b = 0.f;
    #pragma unroll
    for (int k = 0; k < 8; k++) {
        r += t[3*k+0]; g += t[3*k+1]; b += t[3*k+2];
    }
    g_COL[f] = make_float4(r*0.125f, g*0.125f, b*0.125f, 0.f);
}

// ---------------- kernel 3: cull + rasterize + per-block loss partials -------
__global__ __launch_bounds__(256)
void k_render(const float* __restrict__ image_ref, int nF) {
    __shared__ float4 sA[CH];
    __shared__ float4 sB[CH];
    __shared__ float4 sC[CH];
    __shared__ int    sIdx[CH];
    __shared__ int    sCnt;
    __shared__ float  sRed[256];

    const int tx = threadIdx.x, ty = threadIdx.y;
    const int tid = ty * 16 + tx;
    const int x  = blockIdx.x * TILE_W + tx;
    const int y0 = blockIdx.y * TILE_H + ty;       // first pixel row
    // second pixel row = y0 + 16

    const float px  = (x  + 0.5f) * (2.0f / WW) - 1.0f;
    const float py0 = 1.0f - (y0 + 0.5f) * (2.0f / HH);
    const float dpy = -16.0f * (2.0f / HH);        // py1 = py0 + dpy

    // tile NDC bounds for culling
    const float txmin = (blockIdx.x * TILE_W + 0.5f) * (2.0f / WW) - 1.0f;
    const float txmax = (blockIdx.x * TILE_W + TILE_W - 0.5f) * (2.0f / WW) - 1.0f;
    const float tymax = 1.0f - (blockIdx.y * TILE_H + 0.5f) * (2.0f / HH);
    const float tymin = 1.0f - (blockIdx.y * TILE_H + TILE_H - 0.5f) * (2.0f / HH);

    float zb0 = BIGZ, zb1 = BIGZ;
    int   b0  = -1,   b1  = -1;

    for (int base = 0; base < nF; base += CH) {
        __syncthreads();
        if (tid == 0) sCnt = 0;
        __syncthreads();

        int f = base + tid;
        if (f < nF) {
            float4 bb = g_BB[f];
            bool ok = (bb.x <= txmax) && (bb.z >= txmin) &&
                      (bb.y <= tymax) && (bb.w >= tymin);
            if (ok) {
                int p = atomicAdd(&sCnt, 1);
                sIdx[p] = f;
            }
        }
        __syncthreads();
        int cnt = sCnt;
        for (int i = tid; i < cnt; i += 256) {
            int ff = sIdx[i];
            sA[i] = g_FA[ff];
            sB[i] = g_FB[ff];
            sC[i] = g_FC[ff];
        }
        __syncthreads();

        for (int i = 0; i < cnt; i++) {
            float4 fa = sA[i];
            float4 fb = sB[i];
            float4 fc = sC[i];
            int    fi = sIdx[i];
            // pixel 0
            float u0 = fmaf(fa.x, px, fmaf(fa.y, py0, fa.z));
            float u1 = fmaf(fa.w, px, fmaf(fb.x, py0, fb.y));
            float u2 = fmaf(fb.z, px, fmaf(fb.w, py0, fc.x));
            float z  = fmaf(u0, fc.y, fmaf(u1, fc.z, u2 * fc.w));
            float m  = fminf(u0, fminf(u1, u2));
            if (m >= 0.0f && z > NEARP &&
                (z < zb0 || (z == zb0 && fi < b0))) {
                zb0 = z; b0 = fi;
            }
            // pixel 1 (incremental in y)
            float v0 = fmaf(fa.y, dpy, u0);
            float v1 = fmaf(fb.x, dpy, u1);
            float v2 = fmaf(fb.w, dpy, u2);
            float z2 = fmaf(v0, fc.y, fmaf(v1, fc.z, v2 * fc.w));
            float m2 = fminf(v0, fminf(v1, v2));
            if (m2 >= 0.0f && z2 > NEARP &&
                (z2 < zb1 || (z2 == zb1 && fi < b1))) {
                zb1 = z2; b1 = fi;
            }
        }
    }

    float loss = 0.f;
    {
        float r = 0.f, g = 0.f, b = 0.f;
        if (b0 >= 0) { float4 c = g_COL[b0]; r = c.x; g = c.y; b = c.z; }
        int ry = HH - 1 - y0;
        float d0 = r - image_ref[0*HH*WW + ry*WW + x];
        float d1 = g - image_ref[1*HH*WW + ry*WW + x];
        float d2 = b - image_ref[2*HH*WW + ry*WW + x];
        loss += d0*d0 + d1*d1 + d2*d2;
    }
    {
        float r = 0.f, g = 0.f, b = 0.f;
        if (b1 >= 0) { float4 c = g_COL[b1]; r = c.x; g = c.y; b = c.z; }
        int ry = HH - 1 - (y0 + 16);
        float d0 = r - image_ref[0*HH*WW + ry*WW + x];
        float d1 = g - image_ref[1*HH*WW + ry*WW + x];
        float d2 = b - image_ref[2*HH*WW + ry*WW + x];
        loss += d0*d0 + d1*d1 + d2*d2;
    }

    __syncthreads();
    sRed[tid] = loss;
    __syncthreads();
    #pragma unroll
    for (int s = 128; s > 0; s >>= 1) {
        if (tid < s) sRed[tid] += sRed[tid + s];
        __syncthreads();
    }
    if (tid == 0) g_partials[blockIdx.y * gridDim.x + blockIdx.x] = sRed[0];
}

// ---------------- kernel 4: final deterministic reduction ----------------
__global__ void k_reduce(float* __restrict__ out) {
    __shared__ float red[256];
    float s = 0.f;
    for (int i = threadIdx.x; i < NBLK; i += 256) s += g_partials[i];
    red[threadIdx.x] = s;
    __syncthreads();
    #pragma unroll
    for (int st = 128; st > 0; st >>= 1) {
        if (threadIdx.x < st) red[threadIdx.x] += red[threadIdx.x + st];
        __syncthreads();
    }
    if (threadIdx.x == 0) out[0] = red[0];
}

// ---------------- entry point ----------------
extern "C" void kernel_launch(void* const* d_in, const int* in_sizes, int n_in,
                              void* d_out, int out_size) {
    const float* v         = (const float*)d_in[0];   // (1, V, 3)
    const int*   faces     = (const int*)  d_in[1];   // (1, F, 3)
    const float* tex       = (const float*)d_in[2];   // (1, F, 2,2,2,3)
    const float* campos    = (const float*)d_in[3];   // (3,)
    const float* camup     = (const float*)d_in[4];   // (3,)
    const float* image_ref = (const float*)d_in[5];   // (1, 3, H, W)

    int nV = in_sizes[0] / 3;
    int nF = in_sizes[1] / 3;

    k_verts<<<1, 256>>>(v, campos, camup, nV);
    k_faces<<<(nF + 255) / 256, 256>>>(faces, tex, nF);
    k_render<<<dim3(NBX, NBY), dim3(16, 16)>>>(image_ref, nF);
    k_reduce<<<1, 256>>>((float*)d_out);
}

// round 3
// speedup vs baseline: 4.6758x; 1.9173x over previous
#include <cuda_runtime.h>
#include <math.h>

// Problem constants (fixed by the dataset)
#define HH 512
#define WW 512
#define MAXV 2048
#define MAXF 4096
#define SORT_N 4096
#define VIEW_TAN 0.5773502691896258f   // tan(30 deg)
#define NEARP 0.1f
#define BIGZ 1.0e10f
#define CH 256          // faces per culling chunk (= block size)
#define TILE_W 16
#define TILE_H 32       // 2 pixels per thread in y
#define NBX (WW / TILE_W)   // 32
#define NBY (HH / TILE_H)   // 16
#define NBLK (NBX * NBY)    // 512

// ---------------- device scratch (no allocations allowed) ----------------
__device__ float g_vx[MAXV];
__device__ float g_vy[MAXV];
__device__ float g_vz[MAXV];
// Per-face data, 3 x float4 = 12 floats:
//  FA = {A0, B0, C0, A1}
//  FB = {B1, C1, A2, B2}
//  FC = {C2, Z0*inv, Z1*inv, Z2*inv}
__device__ float4 g_FA[MAXF];
__device__ float4 g_FB[MAXF];
__device__ float4 g_FC[MAXF];
__device__ float4 g_BB[MAXF];    // bbox: xmin, ymin, xmax, ymax (NDC)
__device__ float4 g_COL[MAXF];
__device__ float  g_zmin[MAXF];
// z-sorted copies
__device__ float4 g_FA2[MAXF];
__device__ float4 g_FB2[MAXF];
__device__ float4 g_FC2[MAXF];
__device__ float4 g_BB2[MAXF];
__device__ int    g_idx2[MAXF];  // original face index
__device__ float  g_zminS[MAXF];
__device__ int    g_ord[MAXF];
__device__ float  g_partials[NBLK];

// ---------------- kernel 1: camera + vertex transform ----------------
__global__ void k_verts(const float* __restrict__ v,
                        const float* __restrict__ campos,
                        const float* __restrict__ camup,
                        int nV) {
    __shared__ float R[9];
    __shared__ float eye[3];
    if (threadIdx.x == 0) {
        float ex = campos[0], ey = campos[1], ez = campos[2];
        float nx = -ex, ny = -ey, nz = -ez;
        float nl = sqrtf(nx*nx + ny*ny + nz*nz) + 1e-12f;
        float zx = nx/nl, zy = ny/nl, zz = nz/nl;
        float ux = camup[0], uy = camup[1], uz = camup[2];
        float ul = sqrtf(ux*ux + uy*uy + uz*uz) + 1e-12f;
        ux /= ul; uy /= ul; uz /= ul;
        float cx = uy*zz - uz*zy;
        float cy = uz*zx - ux*zz;
        float cz = ux*zy - uy*zx;
        float cl = sqrtf(cx*cx + cy*cy + cz*cz) + 1e-12f;
        float xx = cx/cl, xy = cy/cl, xz = cz/cl;
        float yx = zy*xz - zz*xy;
        float yy = zz*xx - zx*xz;
        float yz = zx*xy - zy*xx;
        R[0]=xx; R[1]=xy; R[2]=xz;
        R[3]=yx; R[4]=yy; R[5]=yz;
        R[6]=zx; R[7]=zy; R[8]=zz;
        eye[0]=ex; eye[1]=ey; eye[2]=ez;
    }
    __syncthreads();
    for (int i = threadIdx.x; i < nV; i += blockDim.x) {
        float ax = v[3*i+0] - eye[0];
        float ay = v[3*i+1] - eye[1];
        float az = v[3*i+2] - eye[2];
        float cxx = R[0]*ax + R[1]*ay + R[2]*az;
        float cyy = R[3]*ax + R[4]*ay + R[5]*az;
        float czz = R[6]*ax + R[7]*ay + R[8]*az;
        float d = czz * VIEW_TAN + 1e-12f;
        g_vx[i] = cxx / d;
        g_vy[i] = cyy / d;
        g_vz[i] = czz;
    }
}

// ---------------- kernel 2: per-face setup (edges, z coeffs, bbox, color) ----
__global__ void k_faces(const int* __restrict__ faces,
                        const float* __restrict__ tex,
                        int nF) {
    int f = blockIdx.x * blockDim.x + threadIdx.x;
    if (f >= nF) return;
    int i0 = faces[3*f+0], i1 = faces[3*f+1], i2 = faces[3*f+2];
    float p0x = g_vx[i0], p0y = g_vy[i0], z0 = g_vz[i0];
    float p1x = g_vx[i1], p1y = g_vy[i1], z1 = g_vz[i1];
    float p2x = g_vx[i2], p2y = g_vy[i2], z2 = g_vz[i2];

    float area = (p1x-p0x)*(p2y-p0y) - (p1y-p0y)*(p2x-p0x);
    float zmn = fminf(z0, fminf(z1, z2));
    float zmx = fmaxf(z0, fmaxf(z1, z2));

    float4 FA, FB, FC, BB;
    bool live = (fabsf(area) > 1e-8f) && (zmx > NEARP);
    if (live) {
        float s   = (area > 0.0f) ? 1.0f : -1.0f;
        float inv = 1.0f / fabsf(area);
        float e0x = (p2x-p1x)*s, e0y = (p2y-p1y)*s;
        float A0 = -e0y, B0 = e0x, C0 = e0y*p1x - e0x*p1y;
        float e1x = (p0x-p2x)*s, e1y = (p0y-p2y)*s;
        float A1 = -e1y, B1 = e1x, C1 = e1y*p2x - e1x*p2y;
        float e2x = (p1x-p0x)*s, e2y = (p1y-p0y)*s;
        float A2 = -e2y, B2 = e2x, C2 = e2y*p0x - e2x*p0y;
        FA = make_float4(A0, B0, C0, A1);
        FB = make_float4(B1, C1, A2, B2);
        FC = make_float4(C2, z0*inv, z1*inv, z2*inv);
        BB = make_float4(fminf(p0x, fminf(p1x, p2x)),
                         fminf(p0y, fminf(p1y, p2y)),
                         fmaxf(p0x, fmaxf(p1x, p2x)),
                         fmaxf(p0y, fmaxf(p1y, p2y)));
    } else {
        FA = make_float4(0.f, 0.f, -1.f, 0.f);
        FB = make_float4(0.f, -1.f, 0.f, 0.f);
        FC = make_float4(-1.f, 0.f, 0.f, 0.f);
        BB = make_float4(2e9f, 2e9f, -2e9f, -2e9f);   // never overlaps any tile
        zmn = 3e38f;                                   // sorts to the very end
    }
    g_FA[f] = FA; g_FB[f] = FB; g_FC[f] = FC; g_BB[f] = BB;
    g_zmin[f] = zmn;

    const float* t = tex + (size_t)f * 24;
    float r = 0.f, g = 0.f, b = 0.f;
    #pragma unroll
    for (int k = 0; k < 8; k++) {
        r += t[3*k+0]; g += t[3*k+1]; b += t[3*k+2];
    }
    g_COL[f] = make_float4(r*0.125f, g*0.125f, b*0.125f, 0.f);
}

// ---------------- kernel 3: bitonic sort by zmin (single block) ----------
__global__ __launch_bounds__(1024)
void k_sort(int nF) {
    __shared__ float key[SORT_N];
    __shared__ int   val[SORT_N];
    const int t = threadIdx.x;
    for (int i = t; i < SORT_N; i += 1024) {
        key[i] = (i < nF) ? g_zmin[i] : 3.3e38f;
        val[i] = i;
    }
    __syncthreads();
    for (int k = 2; k <= SORT_N; k <<= 1) {
        for (int j = k >> 1; j > 0; j >>= 1) {
            for (int i = t; i < SORT_N; i += 1024) {
                int ixj = i ^ j;
                if (ixj > i) {
                    bool up = ((i & k) == 0);
                    float a = key[i], b = key[ixj];
                    if (up ? (a > b) : (a < b)) {
                        key[i] = b; key[ixj] = a;
                        int tv = val[i]; val[i] = val[ixj]; val[ixj] = tv;
                    }
                }
            }
            __syncthreads();
        }
    }
    for (int i = t; i < SORT_N; i += 1024) {
        g_ord[i]   = val[i];
        g_zminS[i] = key[i];
    }
}

// ---------------- kernel 4: scatter face data into sorted order ----------
__global__ void k_reorder(int nF) {
    int i = blockIdx.x * blockDim.x + threadIdx.x;
    if (i >= nF) return;
    int f = g_ord[i];
    g_FA2[i] = g_FA[f];
    g_FB2[i] = g_FB[f];
    g_FC2[i] = g_FC[f];
    g_BB2[i] = g_BB[f];
    g_idx2[i] = f;
}

// ---------------- kernel 5: cull + front-to-back rasterize + loss ---------
__global__ __launch_bounds__(256)
void k_render(const float* __restrict__ image_ref, int nF) {
    __shared__ float4 sA[CH];
    __shared__ float4 sB[CH];
    __shared__ float4 sC[CH];
    __shared__ float  sZm[CH];
    __shared__ int    sIdx[CH];
    __shared__ int    sCnt;
    __shared__ float  sWmax[8];
    __shared__ float  sBmax;
    __shared__ float  sRed[256];

    const int tx = threadIdx.x, ty = threadIdx.y;
    const int tid = ty * 16 + tx;
    const int wid = tid >> 5;
    const int x  = blockIdx.x * TILE_W + tx;
    const int y0 = blockIdx.y * TILE_H + ty;

    const float px  = (x  + 0.5f) * (2.0f / WW) - 1.0f;
    const float py0 = 1.0f - (y0 + 0.5f) * (2.0f / HH);
    const float dpy = -16.0f * (2.0f / HH);        // py1 = py0 + dpy

    const float txmin = (blockIdx.x * TILE_W + 0.5f) * (2.0f / WW) - 1.0f;
    const float txmax = (blockIdx.x * TILE_W + TILE_W - 0.5f) * (2.0f / WW) - 1.0f;
    const float tymax = 1.0f - (blockIdx.y * TILE_H + 0.5f) * (2.0f / HH);
    const float tymin = 1.0f - (blockIdx.y * TILE_H + TILE_H - 0.5f) * (2.0f / HH);

    float zb0 = BIGZ, zb1 = BIGZ;
    int   b0  = -1,   b1  = -1;

    if (tid == 0) sBmax = BIGZ;
    __syncthreads();

    for (int base = 0; base < nF; base += CH) {
        // all remaining faces have zmin >= g_zminS[base]; if that exceeds the
        // farthest current winner in this tile, nothing can change -> done.
        if (g_zminS[base] > sBmax) break;

        if (tid == 0) sCnt = 0;
        __syncthreads();

        int f = base + tid;
        if (f < nF) {
            float4 bb = g_BB2[f];
            bool ok = (bb.x <= txmax) && (bb.z >= txmin) &&
                      (bb.y <= tymax) && (bb.w >= tymin);
            if (ok) {
                int p = atomicAdd(&sCnt, 1);
                sIdx[p] = g_idx2[f];
                sZm[p]  = g_zminS[f];
                sA[p]   = g_FA2[f];
                sB[p]   = g_FB2[f];
                sC[p]   = g_FC2[f];
            }
        }
        __syncthreads();
        int cnt = sCnt;

        // warp-wide upper bound on zbest (conservative, stale within chunk)
        float w = fmaxf(zb0, zb1);
        #pragma unroll
        for (int off = 16; off > 0; off >>= 1)
            w = fmaxf(w, __shfl_xor_sync(0xffffffffu, w, off));

        for (int i = 0; i < cnt; i++) {
            if (sZm[i] > w) continue;   // warp-uniform skip: face can't win
            float4 fa = sA[i];
            float4 fb = sB[i];
            float4 fc = sC[i];
            int    fi = sIdx[i];
            // pixel 0
            float u0 = fmaf(fa.x, px, fmaf(fa.y, py0, fa.z));
            float u1 = fmaf(fa.w, px, fmaf(fb.x, py0, fb.y));
            float u2 = fmaf(fb.z, px, fmaf(fb.w, py0, fc.x));
            float z  = fmaf(u0, fc.y, fmaf(u1, fc.z, u2 * fc.w));
            float m  = fminf(u0, fminf(u1, u2));
            if (m >= 0.0f && z > NEARP &&
                (z < zb0 || (z == zb0 && fi < b0))) {
                zb0 = z; b0 = fi;
            }
            // pixel 1 (incremental in y)
            float v0 = fmaf(fa.y, dpy, u0);
            float v1 = fmaf(fb.x, dpy, u1);
            float v2 = fmaf(fb.w, dpy, u2);
            float z2 = fmaf(v0, fc.y, fmaf(v1, fc.z, v2 * fc.w));
            float m2 = fminf(v0, fminf(v1, v2));
            if (m2 >= 0.0f && z2 > NEARP &&
                (z2 < zb1 || (z2 == zb1 && fi < b1))) {
                zb1 = z2; b1 = fi;
            }
        }

        // refresh block-wide max zbest for the break test
        float m = fmaxf(zb0, zb1);
        #pragma unroll
        for (int off = 16; off > 0; off >>= 1)
            m = fmaxf(m, __shfl_xor_sync(0xffffffffu, m, off));
        if ((tid & 31) == 0) sWmax[wid] = m;
        __syncthreads();
        if (tid == 0) {
            float bm = sWmax[0];
            #pragma unroll
            for (int k = 1; k < 8; k++) bm = fmaxf(bm, sWmax[k]);
            sBmax = bm;
        }
        __syncthreads();
    }

    float loss = 0.f;
    {
        float r = 0.f, g = 0.f, b = 0.f;
        if (b0 >= 0) { float4 c = g_COL[b0]; r = c.x; g = c.y; b = c.z; }
        int ry = HH - 1 - y0;
        float d0 = r - image_ref[0*HH*WW + ry*WW + x];
        float d1 = g - image_ref[1*HH*WW + ry*WW + x];
        float d2 = b - image_ref[2*HH*WW + ry*WW + x];
        loss += d0*d0 + d1*d1 + d2*d2;
    }
    {
        float r = 0.f, g = 0.f, b = 0.f;
        if (b1 >= 0) { float4 c = g_COL[b1]; r = c.x; g = c.y; b = c.z; }
        int ry = HH - 1 - (y0 + 16);
        float d0 = r - image_ref[0*HH*WW + ry*WW + x];
        float d1 = g - image_ref[1*HH*WW + ry*WW + x];
        float d2 = b - image_ref[2*HH*WW + ry*WW + x];
        loss += d0*d0 + d1*d1 + d2*d2;
    }

    __syncthreads();
    sRed[tid] = loss;
    __syncthreads();
    #pragma unroll
    for (int s = 128; s > 0; s >>= 1) {
        if (tid < s) sRed[tid] += sRed[tid + s];
        __syncthreads();
    }
    if (tid == 0) g_partials[blockIdx.y * gridDim.x + blockIdx.x] = sRed[0];
}

// ---------------- kernel 6: final deterministic reduction ----------------
__global__ void k_reduce(float* __restrict__ out) {
    __shared__ float red[256];
    float s = 0.f;
    for (int i = threadIdx.x; i < NBLK; i += 256) s += g_partials[i];
    red[threadIdx.x] = s;
    __syncthreads();
    #pragma unroll
    for (int st = 128; st > 0; st >>= 1) {
        if (threadIdx.x < st) red[threadIdx.x] += red[threadIdx.x + st];
        __syncthreads();
    }
    if (threadIdx.x == 0) out[0] = red[0];
}

// ---------------- entry point ----------------
extern "C" void kernel_launch(void* const* d_in, const int* in_sizes, int n_in,
                              void* d_out, int out_size) {
    const float* v         = (const float*)d_in[0];   // (1, V, 3)
    const int*   faces     = (const int*)  d_in[1];   // (1, F, 3)
    const float* tex       = (const float*)d_in[2];   // (1, F, 2,2,2,3)
    const float* campos    = (const float*)d_in[3];   // (3,)
    const float* camup     = (const float*)d_in[4];   // (3,)
    const float* image_ref = (const float*)d_in[5];   // (1, 3, H, W)

    int nV = in_sizes[0] / 3;
    int nF = in_sizes[1] / 3;

    k_verts<<<1, 256>>>(v, campos, camup, nV);
    k_faces<<<(nF + 255) / 256, 256>>>(faces, tex, nF);
    k_sort<<<1, 1024>>>(nF);
    k_reorder<<<(nF + 255) / 256, 256>>>(nF);
    k_render<<<dim3(NBX, NBY), dim3(16, 16)>>>(image_ref, nF);
    k_reduce<<<1, 256>>>((float*)d_out);
}